// round 7
// baseline (speedup 1.0000x reference)
#include <cuda_runtime.h>
#include <cstdint>

// FRIENDATTN persistent TMA pipeline, 4-stage ring (deep prefetch).
// Per friend-row n (N=16384): scores = x[n]·self[n/64] (L=50,D=128),
// w = softmax(scores); out[n] = sum_l w[l]*mask[n,l]*x[n,l,:].
//
// R5/R6 saturated at ~60% DRAM: only one next-tile in flight per CTA
// (~15.6MB chip-wide) vs the ~16-20MB BW*latency product. This version keeps
// 3 tiles in flight per CTA (4-stage ring, 105KB smem, 2 CTAs/SM -> ~23MB).

#define D_DIM 128
#define L_DIM 50
#define TPB   128
#define NROWS (256 * 64)
#define GRID  304            // 152 SMs * 2 CTAs/SM
#define STAGES 4

#define TILE_FLOATS (L_DIM * D_DIM)       // 6400
#define TILE_BYTES  (TILE_FLOATS * 4)     // 25600
#define SELF_BYTES  (D_DIM * 4)           // 512
#define TX_BYTES    (TILE_BYTES + SELF_BYTES)

// dynamic SMEM layout (float index):
//  sx     [4][6400]   @ 0
//  sself  [4][128]    @ 25600
//  sscore [64]        @ 26112
//  sw     [64]        @ 26176
//  mbar   [4] u64     @ 26240
#define OFF_SELF   25600
#define OFF_SCORE  26112
#define OFF_W      26176
#define OFF_MBAR   26240
#define SM_FLOATS  26248   // 104992 bytes

__device__ __forceinline__ unsigned int smem_u32(const void* p)
{
    return (unsigned int)__cvta_generic_to_shared(p);
}
__device__ __forceinline__ void mbar_init(unsigned int mbar, unsigned int count)
{
    asm volatile("mbarrier.init.shared.b64 [%0], %1;" :: "r"(mbar), "r"(count) : "memory");
}
__device__ __forceinline__ void mbar_expect_tx(unsigned int mbar, unsigned int bytes)
{
    asm volatile("mbarrier.arrive.expect_tx.shared.b64 _, [%0], %1;"
                 :: "r"(mbar), "r"(bytes) : "memory");
}
__device__ __forceinline__ void mbar_wait(unsigned int mbar, unsigned int phase)
{
    asm volatile(
        "{\n\t"
        ".reg .pred P;\n\t"
        "W%=:\n\t"
        "mbarrier.try_wait.parity.acquire.cta.shared::cta.b64 P, [%0], %1, 0x989680;\n\t"
        "@!P bra W%=;\n\t"
        "}"
        :: "r"(mbar), "r"(phase) : "memory");
}
__device__ __forceinline__ void bulk_g2s(unsigned int dst, const void* src,
                                         unsigned int bytes, unsigned int mbar)
{
    asm volatile(
        "cp.async.bulk.shared::cta.global.mbarrier::complete_tx::bytes [%0], [%1], %2, [%3];"
        :: "r"(dst), "l"(src), "r"(bytes), "r"(mbar) : "memory");
}

__global__ __launch_bounds__(TPB) void friendattn_kernel(
    const float* __restrict__ x,        // [N, L, D]
    const float* __restrict__ self_x,   // [B, D]
    const void*  __restrict__ mask,     // [N, L]; dtype detected inline
    float* __restrict__ out)            // [N, D]
{
    extern __shared__ float smem[];
    const int tid  = threadIdx.x;
    const int lane = tid & 31;
    const int warp = tid >> 5;

    const unsigned int mbar_base = smem_u32(smem + OFF_MBAR);

    // ---- inline mask dtype detection (first 2048 int32 words = 8KB, L2-hot) ----
    int gt1 = 0, odd_nz = 0, even_nz = 0;
    {
        const int* mw = (const int*)mask;
        #pragma unroll
        for (int it = 0; it < 16; ++it) {
            int i = it * TPB + tid;
            unsigned int v = (unsigned int)mw[i];
            if (v > 1u) gt1 = 1;
            if (v != 0u) { if (i & 1) odd_nz = 1; else even_nz = 1; }
        }
    }
    const int any_gt1  = __syncthreads_or(gt1);
    const int any_odd  = __syncthreads_or(odd_nz);
    const int any_even = __syncthreads_or(even_nz);
    const int mode = any_gt1 ? 0 : ((!any_odd && any_even) ? 2 : 1);

    if (tid == 0) {
        #pragma unroll
        for (int s = 0; s < STAGES; ++s) mbar_init(mbar_base + 8 * s, 1);
        asm volatile("fence.proxy.async.shared::cta;" ::: "memory");
    }
    __syncthreads();

    // ---- TMA prefetch of one row tile + its self vector into stage s ----
    auto prefetch = [&](int row, int s) {
        const unsigned int mb = mbar_base + 8 * s;
        mbar_expect_tx(mb, TX_BYTES);
        bulk_g2s(smem_u32(smem + s * TILE_FLOATS),
                 x + (size_t)row * TILE_FLOATS, TILE_BYTES, mb);
        bulk_g2s(smem_u32(smem + OFF_SELF + s * D_DIM),
                 self_x + (size_t)(row >> 6) * D_DIM, SELF_BYTES, mb);
    };

    // ---- prologue: fill stages 0..2 ----
    if (tid == 0) {
        #pragma unroll
        for (int k = 0; k < STAGES - 1; ++k) {
            const int r = blockIdx.x + k * GRID;
            if (r < NROWS) prefetch(r, k);
        }
    }

    int row = blockIdx.x;
    int it  = 0;

    while (row < NROWS) {
        const int s = it & (STAGES - 1);
        const unsigned int ph = (unsigned int)((it >> 2) & 1);

        // ---- refill 3 ahead (stage was consumed 3 iterations ago) ----
        {
            const int pf = row + (STAGES - 1) * GRID;
            if (tid == 0 && pf < NROWS) prefetch(pf, (it + STAGES - 1) & (STAGES - 1));
        }

        // ---- softmax warp issues mask loads early (overlap with wait) ----
        float fm0 = 0.0f, fm1 = 0.0f;
        if (warp == 0) {
            const long long mbase = (long long)row * L_DIM;
            if (mode == 0) {
                const unsigned char* m = (const unsigned char*)mask + mbase;
                fm0 = m[lane] ? 1.0f : 0.0f;
                if (lane + 32 < L_DIM) fm1 = m[lane + 32] ? 1.0f : 0.0f;
            } else if (mode == 1) {
                const int* m = (const int*)mask + mbase;
                fm0 = m[lane] ? 1.0f : 0.0f;
                if (lane + 32 < L_DIM) fm1 = m[lane + 32] ? 1.0f : 0.0f;
            } else {
                const int* m = (const int*)mask + 2 * mbase;
                fm0 = m[2 * lane] ? 1.0f : 0.0f;
                if (lane + 32 < L_DIM) fm1 = m[2 * (lane + 32)] ? 1.0f : 0.0f;
            }
        }

        // ---- wait for this stage's TMA ----
        mbar_wait(mbar_base + 8 * s, ph);

        const float* sx    = smem + s * TILE_FLOATS;
        const float* sself = smem + OFF_SELF + s * D_DIM;
        float* sscore = smem + OFF_SCORE;
        float* sw     = smem + OFF_W;

        // ---- scores: warp w handles l = w, w+4, ... ----
        const float4 s4 = ((const float4*)sself)[lane];
        for (int l = warp; l < L_DIM; l += 4) {
            float4 v = ((const float4*)(sx + l * D_DIM))[lane];
            float p = v.x * s4.x + v.y * s4.y + v.z * s4.z + v.w * s4.w;
            #pragma unroll
            for (int o = 16; o > 0; o >>= 1) p += __shfl_xor_sync(0xffffffffu, p, o);
            if (lane == 0) sscore[l] = p;
        }
        __syncthreads();

        // ---- softmax over L=50, mask folded in (warp 0) ----
        if (warp == 0) {
            float v0 = sscore[lane];
            float v1 = (lane + 32 < L_DIM) ? sscore[lane + 32] : -3.0e38f;
            float mx = fmaxf(v0, v1);
            #pragma unroll
            for (int o = 16; o > 0; o >>= 1) mx = fmaxf(mx, __shfl_xor_sync(0xffffffffu, mx, o));
            float e0 = __expf(v0 - mx);
            float e1 = (lane + 32 < L_DIM) ? __expf(v1 - mx) : 0.0f;
            float sum = e0 + e1;
            #pragma unroll
            for (int o = 16; o > 0; o >>= 1) sum += __shfl_xor_sync(0xffffffffu, sum, o);
            float inv = 1.0f / sum;
            sw[lane] = e0 * inv * fm0;
            if (lane + 32 < L_DIM) sw[lane + 32] = e1 * inv * fm1;
        }
        __syncthreads();

        // ---- weighted pooling: thread tid owns output dim d=tid ----
        float acc = 0.0f;
        #pragma unroll
        for (int l = 0; l < L_DIM; ++l)
            acc = fmaf(sw[l], sx[l * D_DIM + tid], acc);
        out[(size_t)row * D_DIM + tid] = acc;

        __syncthreads();   // stage consumed; safe to refill 3 iterations later
        row += GRID;
        ++it;
    }
}

extern "C" void kernel_launch(void* const* d_in, const int* in_sizes, int n_in,
                              void* d_out, int out_size)
{
    const float* x      = (const float*)d_in[0];
    const float* self_x = (const float*)d_in[1];
    const void*  mask   = d_in[n_in - 1];
    float* out = (float*)d_out;

    cudaFuncSetAttribute(friendattn_kernel,
                         cudaFuncAttributeMaxDynamicSharedMemorySize,
                         SM_FLOATS * sizeof(float));

    friendattn_kernel<<<GRID, TPB, SM_FLOATS * sizeof(float)>>>(x, self_x, mask, out);
}

// round 8
// speedup vs baseline: 2.0798x; 2.0798x over previous
#include <cuda_runtime.h>
#include <cstdint>

// FRIENDATTN persistent kernel: single-buffered TMA tile, 8 CTAs/SM.
// Per friend-row n (N=16384): scores = x[n]·self[n/64] (L=50,D=128),
// w = softmax(scores); out[n] = sum_l w[l]*mask[n,l]*x[n,l,:].
//
// R7 falsified the depth hypothesis (23MB in flight -> 37.7% DRAM): DRAM%
// tracks warps/SM (compute-latency coverage). This version maximizes
// independent row streams: one 25.6KB tile per CTA (no double buffer),
// 8 CTAs/SM = 32 warps/SM. Bursty per-CTA demand is smoothed by 1216
// staggered CTAs chip-wide.

#define D_DIM 128
#define L_DIM 50
#define TPB   128
#define NROWS (256 * 64)
#define GRID  1216           // 152 SMs * 8 CTAs/SM

#define TILE_FLOATS (L_DIM * D_DIM)       // 6400
#define TILE_BYTES  (TILE_FLOATS * 4)     // 25600
#define SELF_BYTES  (D_DIM * 4)           // 512
#define TX_BYTES    (TILE_BYTES + SELF_BYTES)

// dynamic SMEM layout (float index):
//  sx     [6400]  @ 0
//  sself  [128]   @ 6400
//  sscore [64]    @ 6528
//  sw     [64]    @ 6592
//  mbar   u64     @ 6656
#define OFF_SELF   6400
#define OFF_SCORE  6528
#define OFF_W      6592
#define OFF_MBAR   6656
#define SM_FLOATS  6658      // 26632 bytes

__device__ __forceinline__ unsigned int smem_u32(const void* p)
{
    return (unsigned int)__cvta_generic_to_shared(p);
}
__device__ __forceinline__ void mbar_init(unsigned int mbar, unsigned int count)
{
    asm volatile("mbarrier.init.shared.b64 [%0], %1;" :: "r"(mbar), "r"(count) : "memory");
}
__device__ __forceinline__ void mbar_expect_tx(unsigned int mbar, unsigned int bytes)
{
    asm volatile("mbarrier.arrive.expect_tx.shared.b64 _, [%0], %1;"
                 :: "r"(mbar), "r"(bytes) : "memory");
}
__device__ __forceinline__ void mbar_wait(unsigned int mbar, unsigned int phase)
{
    asm volatile(
        "{\n\t"
        ".reg .pred P;\n\t"
        "W%=:\n\t"
        "mbarrier.try_wait.parity.acquire.cta.shared::cta.b64 P, [%0], %1, 0x989680;\n\t"
        "@!P bra W%=;\n\t"
        "}"
        :: "r"(mbar), "r"(phase) : "memory");
}
__device__ __forceinline__ void bulk_g2s(unsigned int dst, const void* src,
                                         unsigned int bytes, unsigned int mbar)
{
    asm volatile(
        "cp.async.bulk.shared::cta.global.mbarrier::complete_tx::bytes [%0], [%1], %2, [%3];"
        :: "r"(dst), "l"(src), "r"(bytes), "r"(mbar) : "memory");
}

__global__ __launch_bounds__(TPB) void friendattn_kernel(
    const float* __restrict__ x,        // [N, L, D]
    const float* __restrict__ self_x,   // [B, D]
    const void*  __restrict__ mask,     // [N, L]; dtype detected inline
    float* __restrict__ out)            // [N, D]
{
    extern __shared__ float smem[];
    const int tid  = threadIdx.x;
    const int lane = tid & 31;
    const int warp = tid >> 5;

    const unsigned int mbar = smem_u32(smem + OFF_MBAR);

    // ---- inline mask dtype detection (first 2048 int32 words = 8KB, L2-hot) ----
    int gt1 = 0, odd_nz = 0, even_nz = 0;
    {
        const int* mw = (const int*)mask;
        #pragma unroll
        for (int it = 0; it < 16; ++it) {
            int i = it * TPB + tid;
            unsigned int v = (unsigned int)mw[i];
            if (v > 1u) gt1 = 1;
            if (v != 0u) { if (i & 1) odd_nz = 1; else even_nz = 1; }
        }
    }
    const int any_gt1  = __syncthreads_or(gt1);
    const int any_odd  = __syncthreads_or(odd_nz);
    const int any_even = __syncthreads_or(even_nz);
    const int mode = any_gt1 ? 0 : ((!any_odd && any_even) ? 2 : 1);

    if (tid == 0) {
        mbar_init(mbar, 1);
        asm volatile("fence.proxy.async.shared::cta;" ::: "memory");
    }
    __syncthreads();

    // ---- TMA prefetch: whole row tile + self vector, one mbar ----
    auto prefetch = [&](int row) {
        mbar_expect_tx(mbar, TX_BYTES);
        bulk_g2s(smem_u32(smem), x + (size_t)row * TILE_FLOATS, TILE_BYTES, mbar);
        bulk_g2s(smem_u32(smem + OFF_SELF),
                 self_x + (size_t)(row >> 6) * D_DIM, SELF_BYTES, mbar);
    };

    int row = blockIdx.x;
    if (tid == 0 && row < NROWS) prefetch(row);

    unsigned int phase = 0u;

    while (row < NROWS) {
        // ---- softmax warp issues mask loads early (overlap with wait) ----
        float fm0 = 0.0f, fm1 = 0.0f;
        if (warp == 0) {
            const long long mbase = (long long)row * L_DIM;
            if (mode == 0) {
                const unsigned char* m = (const unsigned char*)mask + mbase;
                fm0 = m[lane] ? 1.0f : 0.0f;
                if (lane + 32 < L_DIM) fm1 = m[lane + 32] ? 1.0f : 0.0f;
            } else if (mode == 1) {
                const int* m = (const int*)mask + mbase;
                fm0 = m[lane] ? 1.0f : 0.0f;
                if (lane + 32 < L_DIM) fm1 = m[lane + 32] ? 1.0f : 0.0f;
            } else {
                const int* m = (const int*)mask + 2 * mbase;
                fm0 = m[2 * lane] ? 1.0f : 0.0f;
                if (lane + 32 < L_DIM) fm1 = m[2 * (lane + 32)] ? 1.0f : 0.0f;
            }
        }

        // ---- wait for this row's TMA ----
        mbar_wait(mbar, phase);
        phase ^= 1u;

        const float* sx    = smem;
        const float* sself = smem + OFF_SELF;
        float* sscore = smem + OFF_SCORE;
        float* sw     = smem + OFF_W;

        // ---- scores: warp w handles l = w, w+4, ... ----
        const float4 s4 = ((const float4*)sself)[lane];
        for (int l = warp; l < L_DIM; l += 4) {
            float4 v = ((const float4*)(sx + l * D_DIM))[lane];
            float p = v.x * s4.x + v.y * s4.y + v.z * s4.z + v.w * s4.w;
            #pragma unroll
            for (int o = 16; o > 0; o >>= 1) p += __shfl_xor_sync(0xffffffffu, p, o);
            if (lane == 0) sscore[l] = p;
        }
        __syncthreads();

        // ---- softmax over L=50, mask folded in (warp 0) ----
        if (warp == 0) {
            float v0 = sscore[lane];
            float v1 = (lane + 32 < L_DIM) ? sscore[lane + 32] : -3.0e38f;
            float mx = fmaxf(v0, v1);
            #pragma unroll
            for (int o = 16; o > 0; o >>= 1) mx = fmaxf(mx, __shfl_xor_sync(0xffffffffu, mx, o));
            float e0 = __expf(v0 - mx);
            float e1 = (lane + 32 < L_DIM) ? __expf(v1 - mx) : 0.0f;
            float sum = e0 + e1;
            #pragma unroll
            for (int o = 16; o > 0; o >>= 1) sum += __shfl_xor_sync(0xffffffffu, sum, o);
            float inv = 1.0f / sum;
            sw[lane] = e0 * inv * fm0;
            if (lane + 32 < L_DIM) sw[lane + 32] = e1 * inv * fm1;
        }
        __syncthreads();

        // ---- weighted pooling: thread tid owns output dim d=tid ----
        float acc = 0.0f;
        #pragma unroll
        for (int l = 0; l < L_DIM; ++l)
            acc = fmaf(sw[l], sx[l * D_DIM + tid], acc);
        out[(size_t)row * D_DIM + tid] = acc;

        __syncthreads();   // all smem reads done -> safe to refill the single buffer

        row += GRID;
        if (tid == 0 && row < NROWS) prefetch(row);
    }
}

extern "C" void kernel_launch(void* const* d_in, const int* in_sizes, int n_in,
                              void* d_out, int out_size)
{
    const float* x      = (const float*)d_in[0];
    const float* self_x = (const float*)d_in[1];
    const void*  mask   = d_in[n_in - 1];
    float* out = (float*)d_out;

    cudaFuncSetAttribute(friendattn_kernel,
                         cudaFuncAttributeMaxDynamicSharedMemorySize,
                         SM_FLOATS * sizeof(float));

    friendattn_kernel<<<GRID, TPB, SM_FLOATS * sizeof(float)>>>(x, self_x, mask, out);
}